// round 1
// baseline (speedup 1.0000x reference)
#include <cuda_runtime.h>

#define HF 64
#define WF 64
#define NPIX 4096
#define M_TOT 48
#define DCH 256
#define NGF 16

__device__ float g_A[M_TOT * NPIX];
__device__ float g_SA[M_TOT];
__device__ float g_u[M_TOT * DCH];

// ---------------------------------------------------------------------------
// K0: zero the scatter buffer A and SA
// grid 192 x 256 threads, each thread one float4 of A
// ---------------------------------------------------------------------------
__global__ void k_zero() {
    int idx = blockIdx.x * blockDim.x + threadIdx.x;   // 0..49151
    float4* A4 = reinterpret_cast<float4*>(g_A);
    A4[idx] = make_float4(0.f, 0.f, 0.f, 0.f);
    if (idx < M_TOT) g_SA[idx] = 0.f;
}

// ---------------------------------------------------------------------------
// K1: flow downsample (exact 2x2 average of p_motions at rows/cols 4i+1,4i+2,
// scaled by 0.25) + bilinear scatter of weights into A, accumulate SA.
// grid 192 (4 blocks per m), block 256. Each thread handles 4 dest pixels.
// ---------------------------------------------------------------------------
__global__ void __launch_bounds__(256) k_flow_scatter(const float* __restrict__ pmot) {
    int m = blockIdx.x >> 2;
    int q = blockIdx.x & 3;
    const float* pm = pmot + (size_t)m * 2u * 65536u;   // (b*12+tp) flattened == m
    float* Am = g_A + m * NPIX;
    const float inv = 1.0f / 4096.0f;
    float wsum = 0.f;

#pragma unroll
    for (int k = 0; k < 4; k++) {
        int p = q * 1024 + k * 256 + threadIdx.x;   // dest pixel 0..4095
        int i = p >> 6;
        int j = p & 63;
        const float* r = pm + (4 * i + 1) * 256 + (4 * j + 1);
        float fy = (r[0] + r[1] + r[256] + r[257]) * 0.0625f;          // avg*0.25
        const float* rx = r + 65536;
        float fx = (rx[0] + rx[1] + rx[256] + rx[257]) * 0.0625f;

        float y = (float)i + fy;
        float x = (float)j + fx;
        float y0f = floorf(y), x0f = floorf(x);
        float wy = y - y0f, wx = x - x0f;
        int y0 = (int)y0f, x0 = (int)x0f;
        int y1 = y0 + 1, x1 = x0 + 1;

        float w00 = (1.f - wy) * (1.f - wx) * inv;
        float w01 = (1.f - wy) * wx * inv;
        float w10 = wy * (1.f - wx) * inv;
        float w11 = wy * wx * inv;

        bool vy0 = (y0 >= 0) & (y0 < HF);
        bool vy1 = (y1 >= 0) & (y1 < HF);
        bool vx0 = (x0 >= 0) & (x0 < WF);
        bool vx1 = (x1 >= 0) & (x1 < WF);

        if (vy0 & vx0) { atomicAdd(Am + y0 * WF + x0, w00); wsum += w00; }
        if (vy0 & vx1) { atomicAdd(Am + y0 * WF + x1, w01); wsum += w01; }
        if (vy1 & vx0) { atomicAdd(Am + y1 * WF + x0, w10); wsum += w10; }
        if (vy1 & vx1) { atomicAdd(Am + y1 * WF + x1, w11); wsum += w11; }
    }

#pragma unroll
    for (int off = 16; off; off >>= 1)
        wsum += __shfl_down_sync(0xffffffffu, wsum, off);
    if ((threadIdx.x & 31) == 0) atomicAdd(&g_SA[m], wsum);
}

// ---------------------------------------------------------------------------
// K2: u[m][c] = dot(A[m], i_features[gf][c])  for the 3 m's sharing gf.
// grid (16 gf, 16 ctiles), block 256. A weights (48 floats) in registers,
// 16 channels per block, double-buffered float4 feature loads, warp-shuffle
// reduce into shared, single final barrier.
// ---------------------------------------------------------------------------
__global__ void __launch_bounds__(256) k_reduce(const float* __restrict__ feat) {
    int gf = blockIdx.x;            // 0..15  == b*4+g
    int b = gf >> 2, g = gf & 3;
    int m0 = b * 12 + g * 3;        // 3 consecutive m's use this gf

    const float4* A4 = reinterpret_cast<const float4*>(g_A);
    float4 a[3][4];
#pragma unroll
    for (int r = 0; r < 3; r++)
#pragma unroll
        for (int k = 0; k < 4; k++)
            a[r][k] = A4[(m0 + r) * 1024 + k * 256 + threadIdx.x];

    __shared__ float red[16][8][3];
    int warp = threadIdx.x >> 5;
    int lane = threadIdx.x & 31;

    const float4* F4 = reinterpret_cast<const float4*>(feat)
                     + (size_t)gf * DCH * 1024
                     + (size_t)blockIdx.y * 16 * 1024;

    float4 cur[4], nxt[4];
#pragma unroll
    for (int k = 0; k < 4; k++) cur[k] = F4[k * 256 + threadIdx.x];

    for (int ch = 0; ch < 16; ch++) {
        if (ch < 15) {
#pragma unroll
            for (int k = 0; k < 4; k++)
                nxt[k] = F4[(ch + 1) * 1024 + k * 256 + threadIdx.x];
        }
        float acc0 = 0.f, acc1 = 0.f, acc2 = 0.f;
#pragma unroll
        for (int k = 0; k < 4; k++) {
            float4 f = cur[k];
            acc0 += a[0][k].x * f.x + a[0][k].y * f.y + a[0][k].z * f.z + a[0][k].w * f.w;
            acc1 += a[1][k].x * f.x + a[1][k].y * f.y + a[1][k].z * f.z + a[1][k].w * f.w;
            acc2 += a[2][k].x * f.x + a[2][k].y * f.y + a[2][k].z * f.z + a[2][k].w * f.w;
        }
#pragma unroll
        for (int off = 16; off; off >>= 1) {
            acc0 += __shfl_down_sync(0xffffffffu, acc0, off);
            acc1 += __shfl_down_sync(0xffffffffu, acc1, off);
            acc2 += __shfl_down_sync(0xffffffffu, acc2, off);
        }
        if (lane == 0) {
            red[ch][warp][0] = acc0;
            red[ch][warp][1] = acc1;
            red[ch][warp][2] = acc2;
        }
        if (ch < 15) {
#pragma unroll
            for (int k = 0; k < 4; k++) cur[k] = nxt[k];
        }
    }
    __syncthreads();

    if (threadIdx.x < 48) {
        int ch = threadIdx.x / 3;
        int r  = threadIdx.x % 3;
        float s = 0.f;
#pragma unroll
        for (int w = 0; w < 8; w++) s += red[ch][w][r];
        g_u[(m0 + r) * DCH + blockIdx.y * 16 + ch] = s;
    }
}

// ---------------------------------------------------------------------------
// K3: per-m double GEMV:
//   s[c]  = sum_c' W_emb[c,c'] * u[m,c'] + b_emb[c]*SA[m]
//   out[o]= sum_c  W_dc[o,c]  * s[c]     + b_dc[o]
// grid 48 (one per m), block 256. W staged in shared (32-col tiles, +1 pad).
// ---------------------------------------------------------------------------
__global__ void __launch_bounds__(256) k_final(
    const float* __restrict__ W_emb, const float* __restrict__ b_emb,
    const float* __restrict__ W_dc,  const float* __restrict__ b_dc,
    float* __restrict__ out)
{
    int m = blockIdx.x;
    int tid = threadIdx.x;

    __shared__ float u_sh[DCH];
    __shared__ float s_sh[DCH];
    __shared__ float Wt[256 * 33];   // 33.8 KB, padded vs bank conflicts

    u_sh[tid] = g_u[m * DCH + tid];
    float sa = g_SA[m];

    float acc = b_emb[tid] * sa;
    for (int t0 = 0; t0 < DCH; t0 += 32) {
        __syncthreads();   // protect prior-tile reads (and u_sh on first iter)
#pragma unroll
        for (int e = 0; e < 32; e++) {
            int idx = e * 256 + tid;          // 0..8191
            int row = idx >> 5, cc = idx & 31;
            Wt[row * 33 + cc] = W_emb[row * 256 + t0 + cc];
        }
        __syncthreads();
#pragma unroll
        for (int cc = 0; cc < 32; cc++)
            acc += Wt[tid * 33 + cc] * u_sh[t0 + cc];
    }
    s_sh[tid] = acc;

    float acc2 = b_dc[tid];
    for (int t0 = 0; t0 < DCH; t0 += 32) {
        __syncthreads();   // also orders s_sh writes before reads
#pragma unroll
        for (int e = 0; e < 32; e++) {
            int idx = e * 256 + tid;
            int row = idx >> 5, cc = idx & 31;
            Wt[row * 33 + cc] = W_dc[row * 256 + t0 + cc];
        }
        __syncthreads();
#pragma unroll
        for (int cc = 0; cc < 32; cc++)
            acc2 += Wt[tid * 33 + cc] * s_sh[t0 + cc];
    }
    out[m * DCH + tid] = acc2;
}

// ---------------------------------------------------------------------------
// inputs (metadata order): imgs, i_features, p_motions, W_emb, b_emb, W_dc, b_dc
// output: float32 [4,4,3,256] = 12288 elements
// ---------------------------------------------------------------------------
extern "C" void kernel_launch(void* const* d_in, const int* in_sizes, int n_in,
                              void* d_out, int out_size) {
    const float* i_features = (const float*)d_in[1];
    const float* p_motions  = (const float*)d_in[2];
    const float* W_emb      = (const float*)d_in[3];
    const float* b_emb      = (const float*)d_in[4];
    const float* W_dc       = (const float*)d_in[5];
    const float* b_dc       = (const float*)d_in[6];
    float* out = (float*)d_out;

    k_zero<<<192, 256>>>();
    k_flow_scatter<<<192, 256>>>(p_motions);
    k_reduce<<<dim3(16, 16), 256>>>(i_features);
    k_final<<<48, 256>>>(W_emb, b_emb, W_dc, b_dc, out);
}

// round 2
// speedup vs baseline: 2.2074x; 2.2074x over previous
#include <cuda_runtime.h>

#define HF 64
#define WF 64
#define NPIX 4096
#define M_TOT 48
#define DCH 256

__device__ float g_A[M_TOT * NPIX];
__device__ float g_SA[M_TOT];
__device__ float g_u[M_TOT * DCH];
__device__ float g_s[M_TOT * DCH];

// ---------------------------------------------------------------------------
// K0: zero the scatter buffer A and SA
// ---------------------------------------------------------------------------
__global__ void k_zero() {
    int idx = blockIdx.x * blockDim.x + threadIdx.x;   // 0..49151
    float4* A4 = reinterpret_cast<float4*>(g_A);
    A4[idx] = make_float4(0.f, 0.f, 0.f, 0.f);
    if (idx < M_TOT) g_SA[idx] = 0.f;
}

// ---------------------------------------------------------------------------
// K1: flow downsample (exact 2x2 average of p_motions at rows/cols 4i+1,4i+2,
// scaled by 0.25) + bilinear scatter of weights into A, accumulate SA.
// ---------------------------------------------------------------------------
__global__ void __launch_bounds__(256) k_flow_scatter(const float* __restrict__ pmot) {
    int m = blockIdx.x >> 2;
    int q = blockIdx.x & 3;
    const float* pm = pmot + (size_t)m * 2u * 65536u;
    float* Am = g_A + m * NPIX;
    const float inv = 1.0f / 4096.0f;
    float wsum = 0.f;

#pragma unroll
    for (int k = 0; k < 4; k++) {
        int p = q * 1024 + k * 256 + threadIdx.x;   // dest pixel 0..4095
        int i = p >> 6;
        int j = p & 63;
        const float* r = pm + (4 * i + 1) * 256 + (4 * j + 1);
        float fy = (r[0] + r[1] + r[256] + r[257]) * 0.0625f;
        const float* rx = r + 65536;
        float fx = (rx[0] + rx[1] + rx[256] + rx[257]) * 0.0625f;

        float y = (float)i + fy;
        float x = (float)j + fx;
        float y0f = floorf(y), x0f = floorf(x);
        float wy = y - y0f, wx = x - x0f;
        int y0 = (int)y0f, x0 = (int)x0f;
        int y1 = y0 + 1, x1 = x0 + 1;

        float w00 = (1.f - wy) * (1.f - wx) * inv;
        float w01 = (1.f - wy) * wx * inv;
        float w10 = wy * (1.f - wx) * inv;
        float w11 = wy * wx * inv;

        bool vy0 = (y0 >= 0) & (y0 < HF);
        bool vy1 = (y1 >= 0) & (y1 < HF);
        bool vx0 = (x0 >= 0) & (x0 < WF);
        bool vx1 = (x1 >= 0) & (x1 < WF);

        if (vy0 & vx0) { atomicAdd(Am + y0 * WF + x0, w00); wsum += w00; }
        if (vy0 & vx1) { atomicAdd(Am + y0 * WF + x1, w01); wsum += w01; }
        if (vy1 & vx0) { atomicAdd(Am + y1 * WF + x0, w10); wsum += w10; }
        if (vy1 & vx1) { atomicAdd(Am + y1 * WF + x1, w11); wsum += w11; }
    }

#pragma unroll
    for (int off = 16; off; off >>= 1)
        wsum += __shfl_down_sync(0xffffffffu, wsum, off);
    if ((threadIdx.x & 31) == 0) atomicAdd(&g_SA[m], wsum);
}

// ---------------------------------------------------------------------------
// K2: u[m][c] = dot(A[m], i_features[gf][c])  for the 3 m's sharing gf.
// grid (16 gf, 16 ctiles), block 256.
// ---------------------------------------------------------------------------
__global__ void __launch_bounds__(256) k_reduce(const float* __restrict__ feat) {
    int gf = blockIdx.x;            // 0..15 == b*4+g
    int b = gf >> 2, g = gf & 3;
    int m0 = b * 12 + g * 3;

    const float4* A4 = reinterpret_cast<const float4*>(g_A);
    float4 a[3][4];
#pragma unroll
    for (int r = 0; r < 3; r++)
#pragma unroll
        for (int k = 0; k < 4; k++)
            a[r][k] = A4[(m0 + r) * 1024 + k * 256 + threadIdx.x];

    __shared__ float red[16][8][3];
    int warp = threadIdx.x >> 5;
    int lane = threadIdx.x & 31;

    const float4* F4 = reinterpret_cast<const float4*>(feat)
                     + (size_t)gf * DCH * 1024
                     + (size_t)blockIdx.y * 16 * 1024;

    float4 cur[4], nxt[4];
#pragma unroll
    for (int k = 0; k < 4; k++) cur[k] = F4[k * 256 + threadIdx.x];

    for (int ch = 0; ch < 16; ch++) {
        if (ch < 15) {
#pragma unroll
            for (int k = 0; k < 4; k++)
                nxt[k] = F4[(ch + 1) * 1024 + k * 256 + threadIdx.x];
        }
        float acc0 = 0.f, acc1 = 0.f, acc2 = 0.f;
#pragma unroll
        for (int k = 0; k < 4; k++) {
            float4 f = cur[k];
            acc0 += a[0][k].x * f.x + a[0][k].y * f.y + a[0][k].z * f.z + a[0][k].w * f.w;
            acc1 += a[1][k].x * f.x + a[1][k].y * f.y + a[1][k].z * f.z + a[1][k].w * f.w;
            acc2 += a[2][k].x * f.x + a[2][k].y * f.y + a[2][k].z * f.z + a[2][k].w * f.w;
        }
#pragma unroll
        for (int off = 16; off; off >>= 1) {
            acc0 += __shfl_down_sync(0xffffffffu, acc0, off);
            acc1 += __shfl_down_sync(0xffffffffu, acc1, off);
            acc2 += __shfl_down_sync(0xffffffffu, acc2, off);
        }
        if (lane == 0) {
            red[ch][warp][0] = acc0;
            red[ch][warp][1] = acc1;
            red[ch][warp][2] = acc2;
        }
        if (ch < 15) {
#pragma unroll
            for (int k = 0; k < 4; k++) cur[k] = nxt[k];
        }
    }
    __syncthreads();

    if (threadIdx.x < 48) {
        int ch = threadIdx.x / 3;
        int r  = threadIdx.x % 3;
        float s = 0.f;
#pragma unroll
        for (int w = 0; w < 8; w++) s += red[ch][w][r];
        g_u[(m0 + r) * DCH + blockIdx.y * 16 + ch] = s;
    }
}

// ---------------------------------------------------------------------------
// K3a: s[m][c] = b_emb[c]*SA[m] + dot(W_emb[c,:], u[m,:])
// grid (32, 48), block 256 (8 warps = 8 output channels per block).
// x row for this m cached in shared; warp-per-output, coalesced W loads.
// ---------------------------------------------------------------------------
__global__ void __launch_bounds__(256) k_gemv_s(
    const float* __restrict__ W_emb, const float* __restrict__ b_emb)
{
    int m = blockIdx.y;
    __shared__ float ush[DCH];
    ush[threadIdx.x] = g_u[m * DCH + threadIdx.x];
    __syncthreads();

    int warp = threadIdx.x >> 5;
    int lane = threadIdx.x & 31;
    int c = blockIdx.x * 8 + warp;

    const float* Wr = W_emb + c * DCH;
    float acc = 0.f;
#pragma unroll
    for (int k = 0; k < 8; k++)
        acc += Wr[k * 32 + lane] * ush[k * 32 + lane];
#pragma unroll
    for (int off = 16; off; off >>= 1)
        acc += __shfl_down_sync(0xffffffffu, acc, off);
    if (lane == 0)
        g_s[m * DCH + c] = acc + b_emb[c] * g_SA[m];
}

// ---------------------------------------------------------------------------
// K3b: out[m][o] = b_dc[o] + dot(W_dc[o,:], s[m,:])
// ---------------------------------------------------------------------------
__global__ void __launch_bounds__(256) k_gemv_out(
    const float* __restrict__ W_dc, const float* __restrict__ b_dc,
    float* __restrict__ out)
{
    int m = blockIdx.y;
    __shared__ float ssh[DCH];
    ssh[threadIdx.x] = g_s[m * DCH + threadIdx.x];
    __syncthreads();

    int warp = threadIdx.x >> 5;
    int lane = threadIdx.x & 31;
    int o = blockIdx.x * 8 + warp;

    const float* Wr = W_dc + o * DCH;
    float acc = 0.f;
#pragma unroll
    for (int k = 0; k < 8; k++)
        acc += Wr[k * 32 + lane] * ssh[k * 32 + lane];
#pragma unroll
    for (int off = 16; off; off >>= 1)
        acc += __shfl_down_sync(0xffffffffu, acc, off);
    if (lane == 0)
        out[m * DCH + o] = acc + b_dc[o];
}

// ---------------------------------------------------------------------------
// inputs (metadata order): imgs, i_features, p_motions, W_emb, b_emb, W_dc, b_dc
// output: float32 [4,4,3,256] = 12288 elements
// ---------------------------------------------------------------------------
extern "C" void kernel_launch(void* const* d_in, const int* in_sizes, int n_in,
                              void* d_out, int out_size) {
    const float* i_features = (const float*)d_in[1];
    const float* p_motions  = (const float*)d_in[2];
    const float* W_emb      = (const float*)d_in[3];
    const float* b_emb      = (const float*)d_in[4];
    const float* W_dc       = (const float*)d_in[5];
    const float* b_dc       = (const float*)d_in[6];
    float* out = (float*)d_out;

    k_zero<<<192, 256>>>();
    k_flow_scatter<<<192, 256>>>(p_motions);
    k_reduce<<<dim3(16, 16), 256>>>(i_features);
    k_gemv_s<<<dim3(32, 48), 256>>>(W_emb, b_emb);
    k_gemv_out<<<dim3(32, 48), 256>>>(W_dc, b_dc, out);
}

// round 3
// speedup vs baseline: 2.6393x; 1.1957x over previous
#include <cuda_runtime.h>

#define HF 64
#define WF 64
#define NPIX 4096
#define M_TOT 48
#define DCH 256

__device__ float g_A[M_TOT * NPIX];
__device__ float g_SA[M_TOT];
__device__ float g_u[M_TOT * DCH];

// ---------------------------------------------------------------------------
// K1: per-m flow downsample + bilinear weight scatter, entirely in shared.
// One block per m (48 blocks, 512 threads, 8 dest pixels/thread).
// Zeroes the tile in-block (no k_zero), shared atomics (no global atomics),
// computes SA as the tile sum during copy-out.
// ---------------------------------------------------------------------------
__global__ void __launch_bounds__(512) k_scatter(const float* __restrict__ pmot) {
    int m = blockIdx.x;
    int tid = threadIdx.x;
    const float* pm = pmot + (size_t)m * 2u * 65536u;

    __shared__ float Ash[NPIX];
    __shared__ float partial[16];

#pragma unroll
    for (int i = 0; i < 8; i++) Ash[i * 512 + tid] = 0.f;
    __syncthreads();

    const float inv = 1.0f / 4096.0f;
#pragma unroll
    for (int k = 0; k < 8; k++) {
        int p = k * 512 + tid;     // dest pixel 0..4095
        int i = p >> 6;
        int j = p & 63;
        const float* r = pm + (4 * i + 1) * 256 + (4 * j + 1);
        float fy = (r[0] + r[1] + r[256] + r[257]) * 0.0625f;   // 2x2 avg * 0.25
        const float* rx = r + 65536;
        float fx = (rx[0] + rx[1] + rx[256] + rx[257]) * 0.0625f;

        float y = (float)i + fy;
        float x = (float)j + fx;
        float y0f = floorf(y), x0f = floorf(x);
        float wy = y - y0f, wx = x - x0f;
        int y0 = (int)y0f, x0 = (int)x0f;
        int y1 = y0 + 1, x1 = x0 + 1;

        float w00 = (1.f - wy) * (1.f - wx) * inv;
        float w01 = (1.f - wy) * wx * inv;
        float w10 = wy * (1.f - wx) * inv;
        float w11 = wy * wx * inv;

        bool vy0 = (y0 >= 0) & (y0 < HF);
        bool vy1 = (y1 >= 0) & (y1 < HF);
        bool vx0 = (x0 >= 0) & (x0 < WF);
        bool vx1 = (x1 >= 0) & (x1 < WF);

        if (vy0 & vx0) atomicAdd(&Ash[y0 * WF + x0], w00);
        if (vy0 & vx1) atomicAdd(&Ash[y0 * WF + x1], w01);
        if (vy1 & vx0) atomicAdd(&Ash[y1 * WF + x0], w10);
        if (vy1 & vx1) atomicAdd(&Ash[y1 * WF + x1], w11);
    }
    __syncthreads();

    // copy out + SA = sum(Ash)
    float4* A4 = reinterpret_cast<float4*>(g_A) + m * 1024;
    const float4* Ash4 = reinterpret_cast<const float4*>(Ash);
    float s = 0.f;
#pragma unroll
    for (int i = 0; i < 2; i++) {
        float4 v = Ash4[i * 512 + tid];
        A4[i * 512 + tid] = v;
        s += v.x + v.y + v.z + v.w;
    }
#pragma unroll
    for (int off = 16; off; off >>= 1)
        s += __shfl_down_sync(0xffffffffu, s, off);
    int warp = tid >> 5, lane = tid & 31;
    if (lane == 0) partial[warp] = s;
    __syncthreads();
    if (warp == 0) {
        float t = (lane < 16) ? partial[lane] : 0.f;
#pragma unroll
        for (int off = 8; off; off >>= 1)
            t += __shfl_down_sync(0xffffffffu, t, off);
        if (lane == 0) g_SA[m] = t;
    }
}

// ---------------------------------------------------------------------------
// K2: u[m][c] = dot(A[m], i_features[gf][c]) for the 3 m's sharing gf.
// grid (16 gf, 32 ctiles of 8 channels), block 256. A weights in registers,
// double-buffered float4 feature loads, warp-shuffle reduce.
// ---------------------------------------------------------------------------
__global__ void __launch_bounds__(256) k_reduce(const float* __restrict__ feat) {
    int gf = blockIdx.x;            // 0..15 == b*4+g
    int b = gf >> 2, g = gf & 3;
    int m0 = b * 12 + g * 3;

    const float4* A4 = reinterpret_cast<const float4*>(g_A);
    float4 a[3][4];
#pragma unroll
    for (int r = 0; r < 3; r++)
#pragma unroll
        for (int k = 0; k < 4; k++)
            a[r][k] = A4[(m0 + r) * 1024 + k * 256 + threadIdx.x];

    __shared__ float red[8][8][3];
    int warp = threadIdx.x >> 5;
    int lane = threadIdx.x & 31;

    const float4* F4 = reinterpret_cast<const float4*>(feat)
                     + (size_t)gf * DCH * 1024
                     + (size_t)blockIdx.y * 8 * 1024;

    float4 cur[4], nxt[4];
#pragma unroll
    for (int k = 0; k < 4; k++) cur[k] = F4[k * 256 + threadIdx.x];

#pragma unroll
    for (int ch = 0; ch < 8; ch++) {
        if (ch < 7) {
#pragma unroll
            for (int k = 0; k < 4; k++)
                nxt[k] = F4[(ch + 1) * 1024 + k * 256 + threadIdx.x];
        }
        float acc0 = 0.f, acc1 = 0.f, acc2 = 0.f;
#pragma unroll
        for (int k = 0; k < 4; k++) {
            float4 f = cur[k];
            acc0 += a[0][k].x * f.x + a[0][k].y * f.y + a[0][k].z * f.z + a[0][k].w * f.w;
            acc1 += a[1][k].x * f.x + a[1][k].y * f.y + a[1][k].z * f.z + a[1][k].w * f.w;
            acc2 += a[2][k].x * f.x + a[2][k].y * f.y + a[2][k].z * f.z + a[2][k].w * f.w;
        }
#pragma unroll
        for (int off = 16; off; off >>= 1) {
            acc0 += __shfl_down_sync(0xffffffffu, acc0, off);
            acc1 += __shfl_down_sync(0xffffffffu, acc1, off);
            acc2 += __shfl_down_sync(0xffffffffu, acc2, off);
        }
        if (lane == 0) {
            red[ch][warp][0] = acc0;
            red[ch][warp][1] = acc1;
            red[ch][warp][2] = acc2;
        }
        if (ch < 7) {
#pragma unroll
            for (int k = 0; k < 4; k++) cur[k] = nxt[k];
        }
    }
    __syncthreads();

    if (threadIdx.x < 24) {
        int ch = threadIdx.x / 3;
        int r  = threadIdx.x % 3;
        float s = 0.f;
#pragma unroll
        for (int w = 0; w < 8; w++) s += red[ch][w][r];
        g_u[(m0 + r) * DCH + blockIdx.y * 8 + ch] = s;
    }
}

// ---------------------------------------------------------------------------
// K3: fused double GEMV per m. 48 blocks x 1024 threads (32 warps).
//   s[c]  = b_emb[c]*SA[m] + dot(W_emb[c,:], u[m,:])
//   out[o]= b_dc[o]        + dot(W_dc[o,:],  s[:])
// Warp per 8 channels per stage; coalesced W row loads; shuffle reduce.
// ---------------------------------------------------------------------------
__global__ void __launch_bounds__(1024) k_final(
    const float* __restrict__ W_emb, const float* __restrict__ b_emb,
    const float* __restrict__ W_dc,  const float* __restrict__ b_dc,
    float* __restrict__ out)
{
    int m = blockIdx.x;
    int tid = threadIdx.x;
    int warp = tid >> 5, lane = tid & 31;

    __shared__ float ush[DCH];
    __shared__ float ssh[DCH];

    if (tid < DCH) ush[tid] = g_u[m * DCH + tid];
    __syncthreads();

    float sa = g_SA[m];

#pragma unroll
    for (int i = 0; i < 8; i++) {
        int c = warp * 8 + i;
        const float* Wr = W_emb + c * DCH;
        float acc = 0.f;
#pragma unroll
        for (int k = 0; k < 8; k++)
            acc += Wr[k * 32 + lane] * ush[k * 32 + lane];
#pragma unroll
        for (int off = 16; off; off >>= 1)
            acc += __shfl_down_sync(0xffffffffu, acc, off);
        if (lane == 0) ssh[c] = acc + b_emb[c] * sa;
    }
    __syncthreads();

#pragma unroll
    for (int i = 0; i < 8; i++) {
        int o = warp * 8 + i;
        const float* Wr = W_dc + o * DCH;
        float acc = 0.f;
#pragma unroll
        for (int k = 0; k < 8; k++)
            acc += Wr[k * 32 + lane] * ssh[k * 32 + lane];
#pragma unroll
        for (int off = 16; off; off >>= 1)
            acc += __shfl_down_sync(0xffffffffu, acc, off);
        if (lane == 0) out[m * DCH + o] = acc + b_dc[o];
    }
}

// ---------------------------------------------------------------------------
// inputs (metadata order): imgs, i_features, p_motions, W_emb, b_emb, W_dc, b_dc
// output: float32 [4,4,3,256] = 12288 elements
// ---------------------------------------------------------------------------
extern "C" void kernel_launch(void* const* d_in, const int* in_sizes, int n_in,
                              void* d_out, int out_size) {
    const float* i_features = (const float*)d_in[1];
    const float* p_motions  = (const float*)d_in[2];
    const float* W_emb      = (const float*)d_in[3];
    const float* b_emb      = (const float*)d_in[4];
    const float* W_dc       = (const float*)d_in[5];
    const float* b_dc       = (const float*)d_in[6];
    float* out = (float*)d_out;

    k_scatter<<<48, 512>>>(p_motions);
    k_reduce<<<dim3(16, 32), 256>>>(i_features);
    k_final<<<48, 1024>>>(W_emb, b_emb, W_dc, b_dc, out);
}